// round 3
// baseline (speedup 1.0000x reference)
#include <cuda_runtime.h>
#include <math.h>

#define NB 4
#define LL 4096
#define SS 4096
#define HH 8
#define DD 64
#define NHD (NB*HH)        // 32
#define NTOK (NB*LL*HH)    // 131072

// ---------------- scratch (device globals; no allocation) ----------------
__device__ float g_kv[NHD*DD*DD];     // [nh][d_k][d_v]
__device__ float g_ksum[NHD*DD];      // [nh][d_k]
__device__ float g_msg[NTOK*DD];      // attention output before merge

// ---------------- k0: zero accumulators ----------------
__global__ void k0_zero() {
    int i = blockIdx.x * blockDim.x + threadIdx.x;
    if (i < NHD*DD*DD) g_kv[i] = 0.f;
    if (i < NHD*DD)    g_ksum[i] = 0.f;
}

// ---------------- k1: k/v projection + kv outer-product accumulation ----------------
// grid: (SS/64, NHD), block 256
#define SCH 64
#define SMEM1 ((64*68*2 + 64*64*3) * 4)

__global__ void k1_kv(const float* __restrict__ src,
                      const float* __restrict__ wk,
                      const float* __restrict__ wv) {
    extern __shared__ float sm[];
    float* wkp  = sm;                  // 64*68 padded, original [e][d] layout
    float* wvp  = wkp + 64*68;
    float* srcb = wvp + 64*68;         // 64*64
    float* ks   = srcb + 64*64;        // elu(k)+1
    float* vs   = ks + 64*64;

    int tid = threadIdx.x;
    int nh = blockIdx.y;
    int n = nh >> 3, h = nh & 7;
    int s0 = blockIdx.x * SCH;

    for (int i = tid; i < 4096; i += 256) {
        int e = i >> 6, d = i & 63;
        wkp[e*68 + d] = wk[i];
        wvp[e*68 + d] = wv[i];
    }
    for (int i = tid; i < SCH*64; i += 256) {
        int s = i >> 6, d = i & 63;
        srcb[i] = src[((n*SS + s0 + s)*HH + h)*64 + d];
    }
    __syncthreads();

    // projection: thread -> e = tid%64, s = tid/64 + 4*it
    {
        int e = tid & 63;
        int sq = tid >> 6;
        const float4* wk4 = (const float4*)(wkp + e*68);
        const float4* wv4 = (const float4*)(wvp + e*68);
        for (int it = 0; it < SCH/4; it++) {
            int s = sq + 4*it;
            const float4* sr4 = (const float4*)(srcb + s*64);
            float ak = 0.f, av = 0.f;
            #pragma unroll
            for (int d4 = 0; d4 < 16; d4++) {
                float4 xv = sr4[d4];
                float4 a = wk4[d4];
                float4 b = wv4[d4];
                ak += xv.x*a.x + xv.y*a.y + xv.z*a.z + xv.w*a.w;
                av += xv.x*b.x + xv.y*b.y + xv.z*b.z + xv.w*b.w;
            }
            ks[s*64 + e] = (ak > 0.f) ? (ak + 1.f) : expf(ak);   // elu(x)+1
            vs[s*64 + e] = av;                                   // (skip /S; cancels with *S)
        }
    }
    __syncthreads();

    // outer product: thread -> ev = tid%64, dk block of 16
    {
        int ev = tid & 63;
        int db = (tid >> 6) * 16;
        float acc[16];
        #pragma unroll
        for (int i = 0; i < 16; i++) acc[i] = 0.f;
        for (int s = 0; s < SCH; s++) {
            float vv = vs[s*64 + ev];
            const float4* kr = (const float4*)(ks + s*64 + db);
            #pragma unroll
            for (int q = 0; q < 4; q++) {
                float4 kq = kr[q];
                acc[4*q+0] += kq.x * vv;
                acc[4*q+1] += kq.y * vv;
                acc[4*q+2] += kq.z * vv;
                acc[4*q+3] += kq.w * vv;
            }
        }
        float* kvg = g_kv + nh*4096;
        #pragma unroll
        for (int i = 0; i < 16; i++)
            atomicAdd(kvg + (db + i)*64 + ev, acc[i]);
    }

    // ksum
    if (tid < 64) {
        float s = 0.f;
        for (int i = 0; i < SCH; i++) s += ks[i*64 + tid];
        atomicAdd(g_ksum + nh*64 + tid, s);
    }
}

// ---------------- k2: q projection + attention apply ----------------
// grid: (LL/128, NHD), block 256 (8 warps, warp-per-token)
#define SMEM2 ((64*68*2 + 64 + 8*64*2) * 4)

__global__ void k2_attn(const float* __restrict__ x,
                        const float* __restrict__ wq) {
    extern __shared__ float sm[];
    float* wqp  = sm;                 // 64*68
    float* kvT  = wqp + 64*68;        // kvT[v][d] padded 68
    float* ksb  = kvT + 64*68;        // 64
    float* xbuf = ksb + 64;           // 8*64
    float* qbuf = xbuf + 8*64;        // 8*64

    int tid = threadIdx.x;
    int nh = blockIdx.y;
    int n = nh >> 3, h = nh & 7;
    int l0 = blockIdx.x * 128;

    for (int i = tid; i < 4096; i += 256) {
        wqp[(i >> 6)*68 + (i & 63)] = wq[i];
        kvT[(i & 63)*68 + (i >> 6)] = g_kv[nh*4096 + i];   // transpose
    }
    if (tid < 64) ksb[tid] = g_ksum[nh*64 + tid];
    __syncthreads();

    int w = tid >> 5, lane = tid & 31;
    float* xb = xbuf + w*64;
    float* qb = qbuf + w*64;

    for (int it = 0; it < 16; it++) {
        int l = l0 + w + 8*it;
        int row = (n*LL + l)*HH + h;
        const float* xr = x + row*64;
        xb[lane]      = xr[lane];
        xb[lane + 32] = xr[lane + 32];
        __syncwarp();

        // q = elu(x @ wq^T) + 1 for e = lane, lane+32
        float q0 = 0.f, q1 = 0.f;
        {
            const float4* x4 = (const float4*)xb;
            const float4* a4 = (const float4*)(wqp + lane*68);
            const float4* b4 = (const float4*)(wqp + (lane+32)*68);
            #pragma unroll
            for (int d4 = 0; d4 < 16; d4++) {
                float4 xv = x4[d4];
                float4 a = a4[d4], b = b4[d4];
                q0 += xv.x*a.x + xv.y*a.y + xv.z*a.z + xv.w*a.w;
                q1 += xv.x*b.x + xv.y*b.y + xv.z*b.z + xv.w*b.w;
            }
        }
        q0 = (q0 > 0.f) ? (q0 + 1.f) : expf(q0);
        q1 = (q1 > 0.f) ? (q1 + 1.f) : expf(q1);
        qb[lane]      = q0;
        qb[lane + 32] = q1;

        float zp = q0*ksb[lane] + q1*ksb[lane + 32];
        #pragma unroll
        for (int o = 16; o > 0; o >>= 1) zp += __shfl_xor_sync(0xffffffffu, zp, o);
        float z = 1.f / (zp + 1e-6f);
        __syncwarp();

        // out[v] = z * sum_d q[d] * kv[d][v]
        float o0 = 0.f, o1 = 0.f;
        {
            const float4* q4 = (const float4*)qb;
            const float4* a4 = (const float4*)(kvT + lane*68);
            const float4* b4 = (const float4*)(kvT + (lane+32)*68);
            #pragma unroll
            for (int d4 = 0; d4 < 16; d4++) {
                float4 qv = q4[d4];
                float4 a = a4[d4], b = b4[d4];
                o0 += qv.x*a.x + qv.y*a.y + qv.z*a.z + qv.w*a.w;
                o1 += qv.x*b.x + qv.y*b.y + qv.z*b.z + qv.w*b.w;
            }
        }
        float* mr = g_msg + row*64;
        mr[lane]      = o0 * z;
        mr[lane + 32] = o1 * z;
        __syncwarp();
    }
}

// ---------------- k3: merge + LN1 + FFN + LN2 + residual ----------------
// grid: 512, block 512 (16 warps, warp-per-token, grid-stride)
#define SMEM3 ((64*68 + 128*132 + 64*132 + 256 + 16*64 + 16*128*2) * 4)

__global__ void k3_ffn(const float* __restrict__ x,
                       const float* __restrict__ wm,
                       const float* __restrict__ w1,
                       const float* __restrict__ w2,
                       const float* __restrict__ g1, const float* __restrict__ b1,
                       const float* __restrict__ g2, const float* __restrict__ b2,
                       float* __restrict__ out) {
    extern __shared__ float sm[];
    float* wmp   = sm;                 // 64*68
    float* w1p   = wmp + 64*68;        // 128*132
    float* w2p   = w1p + 128*132;      // 64*132
    float* gb    = w2p + 64*132;       // 256: g1,b1,g2,b2
    float* mbuf  = gb + 256;           // 16*64
    float* hbuf  = mbuf + 16*64;       // 16*128 concat buffer
    float* h1buf = hbuf + 16*128;      // 16*128

    int tid = threadIdx.x;
    for (int i = tid; i < 4096; i += 512)  wmp[(i >> 6)*68  + (i & 63)]  = wm[i];
    for (int i = tid; i < 16384; i += 512) w1p[(i >> 7)*132 + (i & 127)] = w1[i];
    for (int i = tid; i < 8192; i += 512)  w2p[(i >> 7)*132 + (i & 127)] = w2[i];
    if (tid < 64) {
        gb[tid]       = g1[tid];
        gb[64 + tid]  = b1[tid];
        gb[128 + tid] = g2[tid];
        gb[192 + tid] = b2[tid];
    }
    __syncthreads();

    int w = tid >> 5, lane = tid & 31;
    float* mb  = mbuf + w*64;
    float* hb  = hbuf + w*128;
    float* h1b = h1buf + w*128;
    int wg = blockIdx.x*16 + w;
    int nw = gridDim.x*16;

    for (int tok = wg; tok < NTOK; tok += nw) {
        const float* mr = g_msg + tok*64;
        const float* xr = x + tok*64;
        mb[lane]      = mr[lane];
        mb[lane + 32] = mr[lane + 32];
        float x0 = xr[lane], x1 = xr[lane + 32];
        hb[lane]      = x0;
        hb[lane + 32] = x1;
        __syncwarp();

        // merge GEMV: m @ wmerge^T
        float m0 = 0.f, m1 = 0.f;
        {
            const float4* mv = (const float4*)mb;
            const float4* a4 = (const float4*)(wmp + lane*68);
            const float4* b4 = (const float4*)(wmp + (lane+32)*68);
            #pragma unroll
            for (int d4 = 0; d4 < 16; d4++) {
                float4 m = mv[d4];
                float4 a = a4[d4], b = b4[d4];
                m0 += m.x*a.x + m.y*a.y + m.z*a.z + m.w*a.w;
                m1 += m.x*b.x + m.y*b.y + m.z*b.z + m.w*b.w;
            }
        }
        // LN1
        float s = m0 + m1;
        #pragma unroll
        for (int o = 16; o > 0; o >>= 1) s += __shfl_xor_sync(0xffffffffu, s, o);
        float mean = s * (1.f/64.f);
        float d0 = m0 - mean, d1 = m1 - mean;
        float v = d0*d0 + d1*d1;
        #pragma unroll
        for (int o = 16; o > 0; o >>= 1) v += __shfl_xor_sync(0xffffffffu, v, o);
        float inv = rsqrtf(v * (1.f/64.f) + 1e-5f);
        hb[64 + lane]      = d0*inv*gb[lane]      + gb[64 + lane];
        hb[64 + lane + 32] = d1*inv*gb[lane + 32] + gb[64 + lane + 32];
        __syncwarp();

        // FFN layer 1: [128] @ w1^T -> relu -> [128]
        {
            float h1[4] = {0.f, 0.f, 0.f, 0.f};
            const float4* hv = (const float4*)hb;
            #pragma unroll
            for (int d4 = 0; d4 < 32; d4++) {
                float4 hx = hv[d4];
                #pragma unroll
                for (int j = 0; j < 4; j++) {
                    float4 wv = ((const float4*)(w1p + (lane + 32*j)*132))[d4];
                    h1[j] += hx.x*wv.x + hx.y*wv.y + hx.z*wv.z + hx.w*wv.w;
                }
            }
            #pragma unroll
            for (int j = 0; j < 4; j++) h1b[lane + 32*j] = fmaxf(h1[j], 0.f);
        }
        __syncwarp();

        // FFN layer 2: [128] @ w2^T -> [64]
        float o0 = 0.f, o1 = 0.f;
        {
            const float4* hv = (const float4*)h1b;
            const float4* a4 = (const float4*)(w2p + lane*132);
            const float4* b4 = (const float4*)(w2p + (lane+32)*132);
            #pragma unroll
            for (int d4 = 0; d4 < 32; d4++) {
                float4 hx = hv[d4];
                float4 a = a4[d4], b = b4[d4];
                o0 += hx.x*a.x + hx.y*a.y + hx.z*a.z + hx.w*a.w;
                o1 += hx.x*b.x + hx.y*b.y + hx.z*b.z + hx.w*b.w;
            }
        }
        // LN2 + residual
        float s2 = o0 + o1;
        #pragma unroll
        for (int o = 16; o > 0; o >>= 1) s2 += __shfl_xor_sync(0xffffffffu, s2, o);
        float mean2 = s2 * (1.f/64.f);
        float e0 = o0 - mean2, e1 = o1 - mean2;
        float v2 = e0*e0 + e1*e1;
        #pragma unroll
        for (int o = 16; o > 0; o >>= 1) v2 += __shfl_xor_sync(0xffffffffu, v2, o);
        float inv2 = rsqrtf(v2 * (1.f/64.f) + 1e-5f);

        out[tok*64 + lane]      = x0 + e0*inv2*gb[128 + lane]      + gb[192 + lane];
        out[tok*64 + lane + 32] = x1 + e1*inv2*gb[128 + lane + 32] + gb[192 + lane + 32];
        __syncwarp();
    }
}

// ---------------- launch ----------------
extern "C" void kernel_launch(void* const* d_in, const int* in_sizes, int n_in,
                              void* d_out, int out_size) {
    const float* x   = (const float*)d_in[0];
    const float* src = (const float*)d_in[1];
    const float* wq  = (const float*)d_in[2];
    const float* wk  = (const float*)d_in[3];
    const float* wv  = (const float*)d_in[4];
    const float* wm  = (const float*)d_in[5];
    const float* w1  = (const float*)d_in[6];
    const float* w2  = (const float*)d_in[7];
    const float* g1  = (const float*)d_in[8];
    const float* b1  = (const float*)d_in[9];
    const float* g2  = (const float*)d_in[10];
    const float* b2  = (const float*)d_in[11];
    float* out = (float*)d_out;

    cudaFuncSetAttribute(k1_kv,  cudaFuncAttributeMaxDynamicSharedMemorySize, SMEM1);
    cudaFuncSetAttribute(k3_ffn, cudaFuncAttributeMaxDynamicSharedMemorySize, SMEM3);

    k0_zero<<<512, 256>>>();
    k1_kv<<<dim3(SS/SCH, NHD), 256, SMEM1>>>(src, wk, wv);
    k2_attn<<<dim3(LL/128, NHD), 256, SMEM2>>>(x, wq);
    k3_ffn<<<512, 512, SMEM3>>>(x, wm, w1, w2, g1, b1, g2, b2, out);
}

// round 5
// speedup vs baseline: 1.8414x; 1.8414x over previous
#include <cuda_runtime.h>
#include <math.h>

#define NB 4
#define LL 4096
#define SS 4096
#define HH 8
#define NHD 32
#define NTOK (NB*LL*HH)    // 131072

// ---------------- scratch ----------------
__device__ float g_kv[NHD*64*64];     // [nh][d_k][d_v]
__device__ float g_ksum[NHD*64];
__device__ float g_msg[NTOK*64];

// ---------------- k0 ----------------
__global__ void k0_zero() {
    int i = blockIdx.x * blockDim.x + threadIdx.x;
    if (i < NHD*64*64) g_kv[i] = 0.f;
    if (i < NHD*64)    g_ksum[i] = 0.f;
}

// =================================================================
// k1: k/v projection + kv outer product, register-tiled GEMMs
// grid (SS/256, NHD), block 256. smem ~87KB -> 2 CTA/SM
// =================================================================
#define SMEM1_B (5*4352*4)

__global__ __launch_bounds__(256, 2)
void k1_kv(const float* __restrict__ src,
           const float* __restrict__ wk,
           const float* __restrict__ wv) {
    extern __shared__ float sm[];
    float* wkT  = sm;           // [d=64][e=64] stride 68
    float* wvT  = wkT + 4352;
    float* srcT = wvT + 4352;   // [d][s] stride 68
    float* ksS  = srcT + 4352;  // [s][dk] stride 68  (elu(k)+1)
    float* vsS  = ksS + 4352;   // [s][dv] stride 68

    int tid = threadIdx.x;
    int tx = tid & 15, ty = tid >> 4;
    int nh = blockIdx.y, n = nh >> 3, h = nh & 7;

    for (int i = tid; i < 4096; i += 256) {
        int e = i >> 6, d = i & 63;
        wkT[d*68 + e] = wk[i];
        wvT[d*68 + e] = wv[i];
    }

    float acc[4][4];
    #pragma unroll
    for (int i = 0; i < 4; i++)
        #pragma unroll
        for (int j = 0; j < 4; j++) acc[i][j] = 0.f;
    float kreg = 0.f;

    for (int sub = 0; sub < 4; sub++) {
        int s0 = blockIdx.x*256 + sub*64;
        __syncthreads();
        for (int i = tid; i < 4096; i += 256) {
            int s = i >> 6, d = i & 63;
            srcT[d*68 + s] = src[((n*SS + s0 + s)*HH + h)*64 + d];
        }
        __syncthreads();

        // projection GEMM: m=s(ty*4+i), n=e(tx*4+j), k=d
        float ak[4][4], av[4][4];
        #pragma unroll
        for (int i = 0; i < 4; i++)
            #pragma unroll
            for (int j = 0; j < 4; j++) { ak[i][j] = 0.f; av[i][j] = 0.f; }
        #pragma unroll 8
        for (int k = 0; k < 64; k++) {
            float4 a  = *(const float4*)(srcT + k*68 + ty*4);
            float4 bk = *(const float4*)(wkT  + k*68 + tx*4);
            float4 bv = *(const float4*)(wvT  + k*68 + tx*4);
            float aa[4] = {a.x, a.y, a.z, a.w};
            float bkk[4] = {bk.x, bk.y, bk.z, bk.w};
            float bvv[4] = {bv.x, bv.y, bv.z, bv.w};
            #pragma unroll
            for (int i = 0; i < 4; i++)
                #pragma unroll
                for (int j = 0; j < 4; j++) {
                    ak[i][j] += aa[i]*bkk[j];
                    av[i][j] += aa[i]*bvv[j];
                }
        }
        #pragma unroll
        for (int i = 0; i < 4; i++) {
            float4 kw, vw;
            kw.x = (ak[i][0] > 0.f) ? ak[i][0]+1.f : expf(ak[i][0]);
            kw.y = (ak[i][1] > 0.f) ? ak[i][1]+1.f : expf(ak[i][1]);
            kw.z = (ak[i][2] > 0.f) ? ak[i][2]+1.f : expf(ak[i][2]);
            kw.w = (ak[i][3] > 0.f) ? ak[i][3]+1.f : expf(ak[i][3]);
            vw.x = av[i][0]; vw.y = av[i][1]; vw.z = av[i][2]; vw.w = av[i][3];
            *(float4*)(ksS + (ty*4+i)*68 + tx*4) = kw;
            *(float4*)(vsS + (ty*4+i)*68 + tx*4) = vw;
        }
        __syncthreads();

        // outer-product GEMM: m=dk, n=dv, k=s; accumulate across subtiles
        #pragma unroll 8
        for (int k = 0; k < 64; k++) {
            float4 a = *(const float4*)(ksS + k*68 + ty*4);
            float4 b = *(const float4*)(vsS + k*68 + tx*4);
            float aa[4] = {a.x, a.y, a.z, a.w};
            float bb[4] = {b.x, b.y, b.z, b.w};
            #pragma unroll
            for (int i = 0; i < 4; i++)
                #pragma unroll
                for (int j = 0; j < 4; j++)
                    acc[i][j] += aa[i]*bb[j];
        }
        if (tid < 64) {
            #pragma unroll 8
            for (int s = 0; s < 64; s++) kreg += ksS[s*68 + tid];
        }
    }

    float* kvg = g_kv + nh*4096;
    #pragma unroll
    for (int i = 0; i < 4; i++)
        #pragma unroll
        for (int j = 0; j < 4; j++)
            atomicAdd(kvg + (ty*4+i)*64 + tx*4 + j, acc[i][j]);
    if (tid < 64) atomicAdd(g_ksum + nh*64 + tid, kreg);
}

// =================================================================
// k2: q projection + attention apply, register-tiled GEMMs
// grid (LL/64, NHD), block 256. smem ~70KB -> 3 CTA/SM
// =================================================================
#define SMEM2_B ((4*4352 + 128)*4)

__global__ __launch_bounds__(256, 3)
void k2_attn(const float* __restrict__ x,
             const float* __restrict__ wq) {
    extern __shared__ float sm[];
    float* wqT  = sm;           // [d][e] stride 68
    float* kvB  = wqT + 4352;   // [d][v] stride 68
    float* xT   = kvB + 4352;   // [d][t] stride 68
    float* qT   = xT + 4352;    // [e][t] stride 68
    float* ksb  = qT + 4352;    // 64
    float* zbuf = ksb + 64;     // 64

    int tid = threadIdx.x;
    int tx = tid & 15, ty = tid >> 4;
    int nh = blockIdx.y, n = nh >> 3, h = nh & 7;
    int l0 = blockIdx.x * 64;

    for (int i = tid; i < 4096; i += 256) {
        int e = i >> 6, d = i & 63;
        wqT[d*68 + e] = wq[i];
        kvB[e*68 + d] = g_kv[nh*4096 + i];   // kvB[dk][dv] natural
        xT[d*68 + e]  = x[((n*LL + l0 + e)*HH + h)*64 + d];  // e as token idx
    }
    if (tid < 64) ksb[tid] = g_ksum[nh*64 + tid];
    __syncthreads();

    // GEMM1: q_pre = x @ wq^T ; m=token, n=e, k=d
    {
        float acc[4][4];
        #pragma unroll
        for (int i = 0; i < 4; i++)
            #pragma unroll
            for (int j = 0; j < 4; j++) acc[i][j] = 0.f;
        #pragma unroll 8
        for (int k = 0; k < 64; k++) {
            float4 a = *(const float4*)(xT  + k*68 + ty*4);
            float4 b = *(const float4*)(wqT + k*68 + tx*4);
            float aa[4] = {a.x, a.y, a.z, a.w};
            float bb[4] = {b.x, b.y, b.z, b.w};
            #pragma unroll
            for (int i = 0; i < 4; i++)
                #pragma unroll
                for (int j = 0; j < 4; j++)
                    acc[i][j] += aa[i]*bb[j];
        }
        #pragma unroll
        for (int j = 0; j < 4; j++) {
            float4 q4;
            q4.x = (acc[0][j] > 0.f) ? acc[0][j]+1.f : expf(acc[0][j]);
            q4.y = (acc[1][j] > 0.f) ? acc[1][j]+1.f : expf(acc[1][j]);
            q4.z = (acc[2][j] > 0.f) ? acc[2][j]+1.f : expf(acc[2][j]);
            q4.w = (acc[3][j] > 0.f) ? acc[3][j]+1.f : expf(acc[3][j]);
            *(float4*)(qT + (tx*4+j)*68 + ty*4) = q4;  // qT[e][t]
        }
    }
    __syncthreads();

    // z = 1/(q . ksum + eps)
    {
        int t = tid >> 2, q4 = tid & 3;
        float s = 0.f;
        #pragma unroll
        for (int o = 0; o < 16; o++) {
            int idx = q4*16 + o;
            s += qT[idx*68 + t] * ksb[idx];
        }
        s += __shfl_xor_sync(0xffffffffu, s, 1);
        s += __shfl_xor_sync(0xffffffffu, s, 2);
        if (q4 == 0) zbuf[t] = 1.f / (s + 1e-6f);
    }
    __syncthreads();

    // GEMM2: out = q @ kv ; m=token, n=v, k=dk
    {
        float acc[4][4];
        #pragma unroll
        for (int i = 0; i < 4; i++)
            #pragma unroll
            for (int j = 0; j < 4; j++) acc[i][j] = 0.f;
        #pragma unroll 8
        for (int k = 0; k < 64; k++) {
            float4 a = *(const float4*)(qT  + k*68 + ty*4);
            float4 b = *(const float4*)(kvB + k*68 + tx*4);
            float aa[4] = {a.x, a.y, a.z, a.w};
            float bb[4] = {b.x, b.y, b.z, b.w};
            #pragma unroll
            for (int i = 0; i < 4; i++)
                #pragma unroll
                for (int j = 0; j < 4; j++)
                    acc[i][j] += aa[i]*bb[j];
        }
        #pragma unroll
        for (int i = 0; i < 4; i++) {
            int t = ty*4 + i;
            float z = zbuf[t];
            int row = (n*LL + l0 + t)*HH + h;
            float4 o4;
            o4.x = acc[i][0]*z; o4.y = acc[i][1]*z;
            o4.z = acc[i][2]*z; o4.w = acc[i][3]*z;
            *(float4*)(g_msg + row*64 + tx*4) = o4;
        }
    }
}

// =================================================================
// k3: merge + LN1 + FFN + LN2 + residual, persistent block GEMMs
// grid 148, block 256, smem 190KB (weights resident)
// =================================================================
#define SMEM3_B (47616*4)

__global__ __launch_bounds__(256, 1)
void k3_ffn(const float* __restrict__ x,
            const float* __restrict__ wm,
            const float* __restrict__ w1,
            const float* __restrict__ w2,
            const float* __restrict__ g1, const float* __restrict__ b1,
            const float* __restrict__ g2, const float* __restrict__ b2,
            float* __restrict__ out) {
    extern __shared__ float sm[];
    float* wmT = sm;             // [d=64][e=64]  stride 68   (4352)
    float* w1T = wmT + 4352;     // [d=128][e=128] stride 132 (16896)
    float* w2T = w1T + 16896;    // [d=128][e=64]  stride 68  (8704)
    float* hT  = w2T + 8704;     // [k=128][t=64]  stride 68  (8704) rows0-63=x
    float* h1T = hT + 8704;      // [k=128][t=64]  stride 68  (8704) / msgT in rows 0-63
    float* gb  = h1T + 8704;     // 256

    int tid = threadIdx.x;
    int tx = tid & 15, ty = tid >> 4;

    for (int i = tid; i < 4096; i += 256)  { int e = i>>6, d = i&63;  wmT[d*68 + e]  = wm[i]; }
    for (int i = tid; i < 16384; i += 256) { int e = i>>7, d = i&127; w1T[d*132 + e] = w1[i]; }
    for (int i = tid; i < 8192; i += 256)  { int e = i>>7, d = i&127; w2T[d*68 + e]  = w2[i]; }
    if (tid < 64) {
        gb[tid]       = g1[tid];
        gb[64 + tid]  = b1[tid];
        gb[128 + tid] = g2[tid];
        gb[192 + tid] = b2[tid];
    }
    __syncthreads();

    for (int tile = blockIdx.x; tile < NTOK/64; tile += gridDim.x) {
        int tok0 = tile * 64;
        // load tokens: msg -> h1T rows 0-63 (transposed), x -> hT rows 0-63
        for (int i = tid; i < 4096; i += 256) {
            int t = i >> 6, d = i & 63;
            h1T[d*68 + t] = g_msg[(tok0 + t)*64 + d];
            hT[d*68 + t]  = x[(tok0 + t)*64 + d];
        }
        __syncthreads();

        // Stage A: m_pre = msg @ wm^T -> hT rows 64-127
        {
            float acc[4][4];
            #pragma unroll
            for (int i = 0; i < 4; i++)
                #pragma unroll
                for (int j = 0; j < 4; j++) acc[i][j] = 0.f;
            #pragma unroll 8
            for (int k = 0; k < 64; k++) {
                float4 a = *(const float4*)(h1T + k*68 + ty*4);
                float4 b = *(const float4*)(wmT + k*68 + tx*4);
                float aa[4] = {a.x, a.y, a.z, a.w};
                float bb[4] = {b.x, b.y, b.z, b.w};
                #pragma unroll
                for (int i = 0; i < 4; i++)
                    #pragma unroll
                    for (int j = 0; j < 4; j++)
                        acc[i][j] += aa[i]*bb[j];
            }
            #pragma unroll
            for (int j = 0; j < 4; j++) {
                float4 v = {acc[0][j], acc[1][j], acc[2][j], acc[3][j]};
                *(float4*)(hT + (64 + tx*4 + j)*68 + ty*4) = v;
            }
        }
        __syncthreads();

        // LN1 in place on hT rows 64-127
        {
            int t = tid >> 2, q4 = tid & 3;
            float vals[16], s = 0.f, s2 = 0.f;
            #pragma unroll
            for (int o = 0; o < 16; o++) {
                float v = hT[(64 + q4*16 + o)*68 + t];
                vals[o] = v; s += v; s2 += v*v;
            }
            s  += __shfl_xor_sync(0xffffffffu, s, 1);
            s  += __shfl_xor_sync(0xffffffffu, s, 2);
            s2 += __shfl_xor_sync(0xffffffffu, s2, 1);
            s2 += __shfl_xor_sync(0xffffffffu, s2, 2);
            float mean = s * (1.f/64.f);
            float var  = s2 * (1.f/64.f) - mean*mean;
            float inv  = rsqrtf(var + 1e-5f);
            #pragma unroll
            for (int o = 0; o < 16; o++) {
                int idx = q4*16 + o;
                hT[(64 + idx)*68 + t] = (vals[o] - mean)*inv*gb[idx] + gb[64 + idx];
            }
        }
        __syncthreads();

        // Stage B: h1 = relu([x;m] @ w1^T), K=128, N=128 -> h1T
        {
            float acc[4][8];
            #pragma unroll
            for (int i = 0; i < 4; i++)
                #pragma unroll
                for (int j = 0; j < 8; j++) acc[i][j] = 0.f;
            #pragma unroll 8
            for (int k = 0; k < 128; k++) {
                float4 a  = *(const float4*)(hT  + k*68 + ty*4);
                float4 b0 = *(const float4*)(w1T + k*132 + tx*8);
                float4 b1v = *(const float4*)(w1T + k*132 + tx*8 + 4);
                float aa[4] = {a.x, a.y, a.z, a.w};
                float bb[8] = {b0.x, b0.y, b0.z, b0.w, b1v.x, b1v.y, b1v.z, b1v.w};
                #pragma unroll
                for (int i = 0; i < 4; i++)
                    #pragma unroll
                    for (int j = 0; j < 8; j++)
                        acc[i][j] += aa[i]*bb[j];
            }
            #pragma unroll
            for (int j = 0; j < 8; j++) {
                float4 v;
                v.x = fmaxf(acc[0][j], 0.f); v.y = fmaxf(acc[1][j], 0.f);
                v.z = fmaxf(acc[2][j], 0.f); v.w = fmaxf(acc[3][j], 0.f);
                *(float4*)(h1T + (tx*8 + j)*68 + ty*4) = v;
            }
        }
        __syncthreads();

        // Stage C: o = h1 @ w2^T, K=128, N=64 -> hT rows 64-127
        {
            float acc[4][4];
            #pragma unroll
            for (int i = 0; i < 4; i++)
                #pragma unroll
                for (int j = 0; j < 4; j++) acc[i][j] = 0.f;
            #pragma unroll 8
            for (int k = 0; k < 128; k++) {
                float4 a = *(const float4*)(h1T + k*68 + ty*4);
                float4 b = *(const float4*)(w2T + k*68 + tx*4);
                float aa[4] = {a.x, a.y, a.z, a.w};
                float bb[4] = {b.x, b.y, b.z, b.w};
                #pragma unroll
                for (int i = 0; i < 4; i++)
                    #pragma unroll
                    for (int j = 0; j < 4; j++)
                        acc[i][j] += aa[i]*bb[j];
            }
            #pragma unroll
            for (int j = 0; j < 4; j++) {
                float4 v = {acc[0][j], acc[1][j], acc[2][j], acc[3][j]};
                *(float4*)(hT + (64 + tx*4 + j)*68 + ty*4) = v;
            }
        }
        __syncthreads();

        // LN2 + residual -> gmem
        {
            int t = tid >> 2, q4 = tid & 3;
            float vals[16], s = 0.f, s2 = 0.f;
            #pragma unroll
            for (int o = 0; o < 16; o++) {
                float v = hT[(64 + q4*16 + o)*68 + t];
                vals[o] = v; s += v; s2 += v*v;
            }
            s  += __shfl_xor_sync(0xffffffffu, s, 1);
            s  += __shfl_xor_sync(0xffffffffu, s, 2);
            s2 += __shfl_xor_sync(0xffffffffu, s2, 1);
            s2 += __shfl_xor_sync(0xffffffffu, s2, 2);
            float mean = s * (1.f/64.f);
            float var  = s2 * (1.f/64.f) - mean*mean;
            float inv  = rsqrtf(var + 1e-5f);
            #pragma unroll
            for (int o = 0; o < 16; o++) {
                int idx = q4*16 + o;
                out[(tok0 + t)*64 + idx] =
                    hT[idx*68 + t] + (vals[o] - mean)*inv*gb[128 + idx] + gb[192 + idx];
            }
        }
        __syncthreads();
    }
}

// ---------------- launch ----------------
extern "C" void kernel_launch(void* const* d_in, const int* in_sizes, int n_in,
                              void* d_out, int out_size) {
    const float* x   = (const float*)d_in[0];
    const float* src = (const float*)d_in[1];
    const float* wq  = (const float*)d_in[2];
    const float* wk  = (const float*)d_in[3];
    const float* wv  = (const float*)d_in[4];
    const float* wm  = (const float*)d_in[5];
    const float* w1  = (const float*)d_in[6];
    const float* w2  = (const float*)d_in[7];
    const float* g1  = (const float*)d_in[8];
    const float* b1  = (const float*)d_in[9];
    const float* g2  = (const float*)d_in[10];
    const float* b2  = (const float*)d_in[11];
    float* out = (float*)d_out;

    cudaFuncSetAttribute(k1_kv,   cudaFuncAttributeMaxDynamicSharedMemorySize, SMEM1_B);
    cudaFuncSetAttribute(k2_attn, cudaFuncAttributeMaxDynamicSharedMemorySize, SMEM2_B);
    cudaFuncSetAttribute(k3_ffn,  cudaFuncAttributeMaxDynamicSharedMemorySize, SMEM3_B);

    k0_zero<<<512, 256>>>();
    k1_kv<<<dim3(SS/256, NHD), 256, SMEM1_B>>>(src, wk, wv);
    k2_attn<<<dim3(LL/64, NHD), 256, SMEM2_B>>>(x, wq);
    k3_ffn<<<148, 256, SMEM3_B>>>(x, wm, w1, w2, g1, b1, g2, b2, out);
}

// round 7
// speedup vs baseline: 3.0880x; 1.6770x over previous
#include <cuda_runtime.h>
#include <cuda_bf16.h>
#include <math.h>
#include <stdint.h>

#define NB 4
#define LL 4096
#define SS 4096
#define HH 8
#define NHD 32
#define NTOK (NB*LL*HH)    // 131072

// ---------------- scratch ----------------
__device__ float g_kv[NHD*64*64];
__device__ float g_ksum[NHD*64];
__device__ float g_msg[NTOK*64];

// ---------------- k0 ----------------
__global__ void k0_zero() {
    int i = blockIdx.x * blockDim.x + threadIdx.x;
    if (i < NHD*64*64) g_kv[i] = 0.f;
    if (i < NHD*64)    g_ksum[i] = 0.f;
}

// =================================================================
// k1: k/v projection + kv outer product (proven @ R5)
// =================================================================
#define SMEM1_B (5*4352*4)
__global__ __launch_bounds__(256, 2)
void k1_kv(const float* __restrict__ src,
           const float* __restrict__ wk,
           const float* __restrict__ wv) {
    extern __shared__ float sm[];
    float* wkT  = sm;
    float* wvT  = wkT + 4352;
    float* srcT = wvT + 4352;
    float* ksS  = srcT + 4352;
    float* vsS  = ksS + 4352;

    int tid = threadIdx.x;
    int tx = tid & 15, ty = tid >> 4;
    int nh = blockIdx.y, n = nh >> 3, h = nh & 7;

    for (int i = tid; i < 4096; i += 256) {
        int e = i >> 6, d = i & 63;
        wkT[d*68 + e] = wk[i];
        wvT[d*68 + e] = wv[i];
    }

    float acc[4][4];
    #pragma unroll
    for (int i = 0; i < 4; i++)
        #pragma unroll
        for (int j = 0; j < 4; j++) acc[i][j] = 0.f;
    float kreg = 0.f;

    for (int sub = 0; sub < 4; sub++) {
        int s0 = blockIdx.x*256 + sub*64;
        __syncthreads();
        for (int i = tid; i < 4096; i += 256) {
            int s = i >> 6, d = i & 63;
            srcT[d*68 + s] = src[((n*SS + s0 + s)*HH + h)*64 + d];
        }
        __syncthreads();

        float ak[4][4], av[4][4];
        #pragma unroll
        for (int i = 0; i < 4; i++)
            #pragma unroll
            for (int j = 0; j < 4; j++) { ak[i][j] = 0.f; av[i][j] = 0.f; }
        #pragma unroll 8
        for (int k = 0; k < 64; k++) {
            float4 a  = *(const float4*)(srcT + k*68 + ty*4);
            float4 bk = *(const float4*)(wkT  + k*68 + tx*4);
            float4 bv = *(const float4*)(wvT  + k*68 + tx*4);
            float aa[4] = {a.x, a.y, a.z, a.w};
            float bkk[4] = {bk.x, bk.y, bk.z, bk.w};
            float bvv[4] = {bv.x, bv.y, bv.z, bv.w};
            #pragma unroll
            for (int i = 0; i < 4; i++)
                #pragma unroll
                for (int j = 0; j < 4; j++) {
                    ak[i][j] += aa[i]*bkk[j];
                    av[i][j] += aa[i]*bvv[j];
                }
        }
        #pragma unroll
        for (int i = 0; i < 4; i++) {
            float4 kw, vw;
            kw.x = (ak[i][0] > 0.f) ? ak[i][0]+1.f : expf(ak[i][0]);
            kw.y = (ak[i][1] > 0.f) ? ak[i][1]+1.f : expf(ak[i][1]);
            kw.z = (ak[i][2] > 0.f) ? ak[i][2]+1.f : expf(ak[i][2]);
            kw.w = (ak[i][3] > 0.f) ? ak[i][3]+1.f : expf(ak[i][3]);
            vw.x = av[i][0]; vw.y = av[i][1]; vw.z = av[i][2]; vw.w = av[i][3];
            *(float4*)(ksS + (ty*4+i)*68 + tx*4) = kw;
            *(float4*)(vsS + (ty*4+i)*68 + tx*4) = vw;
        }
        __syncthreads();

        #pragma unroll 8
        for (int k = 0; k < 64; k++) {
            float4 a = *(const float4*)(ksS + k*68 + ty*4);
            float4 b = *(const float4*)(vsS + k*68 + tx*4);
            float aa[4] = {a.x, a.y, a.z, a.w};
            float bb[4] = {b.x, b.y, b.z, b.w};
            #pragma unroll
            for (int i = 0; i < 4; i++)
                #pragma unroll
                for (int j = 0; j < 4; j++)
                    acc[i][j] += aa[i]*bb[j];
        }
        if (tid < 64) {
            #pragma unroll 8
            for (int s = 0; s < 64; s++) kreg += ksS[s*68 + tid];
        }
    }

    float* kvg = g_kv + nh*4096;
    #pragma unroll
    for (int i = 0; i < 4; i++)
        #pragma unroll
        for (int j = 0; j < 4; j++)
            atomicAdd(kvg + (ty*4+i)*64 + tx*4 + j, acc[i][j]);
    if (tid < 64) atomicAdd(g_ksum + nh*64 + tid, kreg);
}

// =================================================================
// k2: q projection + attention apply (proven @ R5)
// =================================================================
#define SMEM2_B ((4*4352 + 128)*4)
__global__ __launch_bounds__(256, 3)
void k2_attn(const float* __restrict__ x,
             const float* __restrict__ wq) {
    extern __shared__ float sm[];
    float* wqT  = sm;
    float* kvB  = wqT + 4352;
    float* xT   = kvB + 4352;
    float* qT   = xT + 4352;
    float* ksb  = qT + 4352;
    float* zbuf = ksb + 64;

    int tid = threadIdx.x;
    int tx = tid & 15, ty = tid >> 4;
    int nh = blockIdx.y, n = nh >> 3, h = nh & 7;
    int l0 = blockIdx.x * 64;

    for (int i = tid; i < 4096; i += 256) {
        int e = i >> 6, d = i & 63;
        wqT[d*68 + e] = wq[i];
        kvB[e*68 + d] = g_kv[nh*4096 + i];
        xT[d*68 + e]  = x[((n*LL + l0 + e)*HH + h)*64 + d];
    }
    if (tid < 64) ksb[tid] = g_ksum[nh*64 + tid];
    __syncthreads();

    {
        float acc[4][4];
        #pragma unroll
        for (int i = 0; i < 4; i++)
            #pragma unroll
            for (int j = 0; j < 4; j++) acc[i][j] = 0.f;
        #pragma unroll 8
        for (int k = 0; k < 64; k++) {
            float4 a = *(const float4*)(xT  + k*68 + ty*4);
            float4 b = *(const float4*)(wqT + k*68 + tx*4);
            float aa[4] = {a.x, a.y, a.z, a.w};
            float bb[4] = {b.x, b.y, b.z, b.w};
            #pragma unroll
            for (int i = 0; i < 4; i++)
                #pragma unroll
                for (int j = 0; j < 4; j++)
                    acc[i][j] += aa[i]*bb[j];
        }
        #pragma unroll
        for (int j = 0; j < 4; j++) {
            float4 q4;
            q4.x = (acc[0][j] > 0.f) ? acc[0][j]+1.f : expf(acc[0][j]);
            q4.y = (acc[1][j] > 0.f) ? acc[1][j]+1.f : expf(acc[1][j]);
            q4.z = (acc[2][j] > 0.f) ? acc[2][j]+1.f : expf(acc[2][j]);
            q4.w = (acc[3][j] > 0.f) ? acc[3][j]+1.f : expf(acc[3][j]);
            *(float4*)(qT + (tx*4+j)*68 + ty*4) = q4;
        }
    }
    __syncthreads();

    {
        int t = tid >> 2, q4 = tid & 3;
        float s = 0.f;
        #pragma unroll
        for (int o = 0; o < 16; o++) {
            int idx = q4*16 + o;
            s += qT[idx*68 + t] * ksb[idx];
        }
        s += __shfl_xor_sync(0xffffffffu, s, 1);
        s += __shfl_xor_sync(0xffffffffu, s, 2);
        if (q4 == 0) zbuf[t] = 1.f / (s + 1e-6f);
    }
    __syncthreads();

    {
        float acc[4][4];
        #pragma unroll
        for (int i = 0; i < 4; i++)
            #pragma unroll
            for (int j = 0; j < 4; j++) acc[i][j] = 0.f;
        #pragma unroll 8
        for (int k = 0; k < 64; k++) {
            float4 a = *(const float4*)(qT  + k*68 + ty*4);
            float4 b = *(const float4*)(kvB + k*68 + tx*4);
            float aa[4] = {a.x, a.y, a.z, a.w};
            float bb[4] = {b.x, b.y, b.z, b.w};
            #pragma unroll
            for (int i = 0; i < 4; i++)
                #pragma unroll
                for (int j = 0; j < 4; j++)
                    acc[i][j] += aa[i]*bb[j];
        }
        #pragma unroll
        for (int i = 0; i < 4; i++) {
            int t = ty*4 + i;
            float z = zbuf[t];
            int row = (n*LL + l0 + t)*HH + h;
            float4 o4;
            o4.x = acc[i][0]*z; o4.y = acc[i][1]*z;
            o4.z = acc[i][2]*z; o4.w = acc[i][3]*z;
            *(float4*)(g_msg + row*64 + tx*4) = o4;
        }
    }
}

// =================================================================
// k3: mma.sync bf16x3 merge+LN1+FFN+LN2+residual
// persistent 148 CTAs x 256 threads (8 warps), 64-token tiles
// =================================================================
typedef __nv_bfloat16 bf16;

__device__ __forceinline__ void mma_bf16(float d[4], const uint32_t a[4],
                                         uint32_t b0, uint32_t b1) {
    asm volatile("mma.sync.aligned.m16n8k16.row.col.f32.bf16.bf16.f32 "
        "{%0,%1,%2,%3}, {%4,%5,%6,%7}, {%8,%9}, {%0,%1,%2,%3};"
        : "+f"(d[0]), "+f"(d[1]), "+f"(d[2]), "+f"(d[3])
        : "r"(a[0]), "r"(a[1]), "r"(a[2]), "r"(a[3]), "r"(b0), "r"(b1));
}

__device__ __forceinline__ void split2(float v0, float v1, uint32_t& hi, uint32_t& lo) {
    bf16 h0 = __float2bfloat16(v0);
    bf16 h1 = __float2bfloat16(v1);
    __nv_bfloat162 hh = __halves2bfloat162(h0, h1);
    hi = *(uint32_t*)&hh;
    __nv_bfloat162 ll = __halves2bfloat162(
        __float2bfloat16(v0 - __bfloat162float(h0)),
        __float2bfloat16(v1 - __bfloat162float(h1)));
    lo = *(uint32_t*)&ll;
}

// warp GEMM: M32 (2 mtiles), N = NT*8, K = NK*16, 3-term bf16 split
template<int NT, int NK>
__device__ __forceinline__ void warp_gemm(float acc[2][NT][4],
    const bf16* __restrict__ Ah, const bf16* __restrict__ Al, int sa, int mrow0,
    const bf16* __restrict__ Bh, const bf16* __restrict__ Bl, int sb, int ncol0,
    int lane)
{
    int r = lane >> 2, c2 = (lane & 3)*2;
    #pragma unroll
    for (int ks = 0; ks < NK; ks++) {
        uint32_t ah[2][4], al[2][4];
        #pragma unroll
        for (int mt = 0; mt < 2; mt++) {
            const bf16* pa = Ah + (mrow0 + mt*16 + r)*sa + ks*16 + c2;
            const bf16* pl = Al + (mrow0 + mt*16 + r)*sa + ks*16 + c2;
            ah[mt][0] = *(const uint32_t*)(pa);
            ah[mt][1] = *(const uint32_t*)(pa + 8*sa);
            ah[mt][2] = *(const uint32_t*)(pa + 8);
            ah[mt][3] = *(const uint32_t*)(pa + 8*sa + 8);
            al[mt][0] = *(const uint32_t*)(pl);
            al[mt][1] = *(const uint32_t*)(pl + 8*sa);
            al[mt][2] = *(const uint32_t*)(pl + 8);
            al[mt][3] = *(const uint32_t*)(pl + 8*sa + 8);
        }
        #pragma unroll
        for (int nt = 0; nt < NT; nt++) {
            const bf16* pbh = Bh + (ncol0 + nt*8 + r)*sb + ks*16 + c2;
            const bf16* pbl = Bl + (ncol0 + nt*8 + r)*sb + ks*16 + c2;
            uint32_t bh0 = *(const uint32_t*)(pbh);
            uint32_t bh1 = *(const uint32_t*)(pbh + 8);
            uint32_t bl0 = *(const uint32_t*)(pbl);
            uint32_t bl1 = *(const uint32_t*)(pbl + 8);
            #pragma unroll
            for (int mt = 0; mt < 2; mt++) {
                mma_bf16(acc[mt][nt], ah[mt], bh0, bh1);
                mma_bf16(acc[mt][nt], ah[mt], bl0, bl1);
                mma_bf16(acc[mt][nt], al[mt], bh0, bh1);
            }
        }
    }
}

__device__ __forceinline__ void quad_reduce2(float& s, float& q) {
    s += __shfl_xor_sync(0xffffffffu, s, 1);
    q += __shfl_xor_sync(0xffffffffu, q, 1);
    s += __shfl_xor_sync(0xffffffffu, s, 2);
    q += __shfl_xor_sync(0xffffffffu, q, 2);
}

// smem byte offsets
#define SO_W1H 0
#define SO_W1L 34816
#define SO_W2H 69632
#define SO_W2L 87040
#define SO_WMH 104448
#define SO_WML 113664
#define SO_HH  122880
#define SO_HL  140288
#define SO_H1H 157696
#define SO_H1L 175104
#define SO_XB  192512
#define SO_GB  209408
#define SO_PS  210432
#define SO_PQ  211456
#define SO_MEAN 212480
#define SO_INV 212736
#define SMEM3M 212992

__global__ void __launch_bounds__(256, 1)
k3_mma(const float* __restrict__ x,
       const float* __restrict__ wm,
       const float* __restrict__ w1,
       const float* __restrict__ w2,
       const float* __restrict__ g1, const float* __restrict__ b1,
       const float* __restrict__ g2, const float* __restrict__ b2,
       float* __restrict__ out) {
    extern __shared__ char smem[];
    bf16* W1H = (bf16*)(smem + SO_W1H);
    bf16* W1L = (bf16*)(smem + SO_W1L);
    bf16* W2H = (bf16*)(smem + SO_W2H);
    bf16* W2L = (bf16*)(smem + SO_W2L);
    bf16* WMH = (bf16*)(smem + SO_WMH);
    bf16* WML = (bf16*)(smem + SO_WML);
    bf16* Hh  = (bf16*)(smem + SO_HH);     // [64][136] concat act hi
    bf16* Hl  = (bf16*)(smem + SO_HL);
    bf16* H1h = (bf16*)(smem + SO_H1H);    // [64][136] msg / relu hi
    bf16* H1l = (bf16*)(smem + SO_H1L);
    float* xb    = (float*)(smem + SO_XB); // [64][66]
    float* gbuf  = (float*)(smem + SO_GB);
    float* ps    = (float*)(smem + SO_PS);
    float* pq    = (float*)(smem + SO_PQ);
    float* means = (float*)(smem + SO_MEAN);
    float* invs  = (float*)(smem + SO_INV);

    int tid = threadIdx.x, lane = tid & 31, w = tid >> 5;
    int wM = w & 1, wN = w >> 1;           // 2 x 4 warp grid
    int r = lane >> 2, c2 = (lane & 3)*2;

    // weight split loads (once)
    for (int i = tid; i < 16384; i += 256) {
        int nn = i >> 7, kk = i & 127;
        float v = w1[i];
        bf16 h = __float2bfloat16(v);
        W1H[nn*136 + kk] = h;
        W1L[nn*136 + kk] = __float2bfloat16(v - __bfloat162float(h));
    }
    for (int i = tid; i < 8192; i += 256) {
        int nn = i >> 7, kk = i & 127;
        float v = w2[i];
        bf16 h = __float2bfloat16(v);
        W2H[nn*136 + kk] = h;
        W2L[nn*136 + kk] = __float2bfloat16(v - __bfloat162float(h));
    }
    for (int i = tid; i < 4096; i += 256) {
        int nn = i >> 6, kk = i & 63;
        float v = wm[i];
        bf16 h = __float2bfloat16(v);
        WMH[nn*72 + kk] = h;
        WML[nn*72 + kk] = __float2bfloat16(v - __bfloat162float(h));
    }
    if (tid < 64) {
        gbuf[tid]       = g1[tid];
        gbuf[64 + tid]  = b1[tid];
        gbuf[128 + tid] = g2[tid];
        gbuf[192 + tid] = b2[tid];
    }
    __syncthreads();

    for (int tile = blockIdx.x; tile < NTOK/64; tile += gridDim.x) {
        int tok0 = tile * 64;

        // msg -> H1 (bf16 hi/lo), x -> H cols 0-63 + xbuf fp32
        for (int i = tid; i < 2048; i += 256) {
            int t = i >> 5, j = (i & 31)*2;
            float2 mv = *(const float2*)(g_msg + (size_t)(tok0 + t)*64 + j);
            uint32_t hi, lo;
            split2(mv.x, mv.y, hi, lo);
            *(uint32_t*)(H1h + t*136 + j) = hi;
            *(uint32_t*)(H1l + t*136 + j) = lo;
            float2 xv = *(const float2*)(x + (size_t)(tok0 + t)*64 + j);
            split2(xv.x, xv.y, hi, lo);
            *(uint32_t*)(Hh + t*136 + j) = hi;
            *(uint32_t*)(Hl + t*136 + j) = lo;
            *(float2*)(xb + t*66 + j) = xv;
        }
        __syncthreads();

        // ---- Stage A: msg @ wm^T  (M64,N64,K64) ----
        float accA[2][2][4];
        #pragma unroll
        for (int i = 0; i < 2; i++)
            #pragma unroll
            for (int j = 0; j < 2; j++)
                #pragma unroll
                for (int q = 0; q < 4; q++) accA[i][j][q] = 0.f;
        warp_gemm<2,4>(accA, H1h, H1l, 136, wM*32, WMH, WML, 72, wN*16, lane);

        // LN1 stats
        #pragma unroll
        for (int mt = 0; mt < 2; mt++) {
            float s0 = 0.f, q0 = 0.f, s1 = 0.f, q1 = 0.f;
            #pragma unroll
            for (int nt = 0; nt < 2; nt++) {
                float a0 = accA[mt][nt][0], a1 = accA[mt][nt][1];
                float a2 = accA[mt][nt][2], a3 = accA[mt][nt][3];
                s0 += a0 + a1; q0 += a0*a0 + a1*a1;
                s1 += a2 + a3; q1 += a2*a2 + a3*a3;
            }
            quad_reduce2(s0, q0);
            quad_reduce2(s1, q1);
            if ((lane & 3) == 0) {
                int rr = wM*32 + mt*16 + r;
                ps[rr*4 + wN] = s0;      pq[rr*4 + wN] = q0;
                ps[(rr+8)*4 + wN] = s1;  pq[(rr+8)*4 + wN] = q1;
            }
        }
        __syncthreads();
        if (tid < 64) {
            float s = ps[tid*4] + ps[tid*4+1] + ps[tid*4+2] + ps[tid*4+3];
            float q = pq[tid*4] + pq[tid*4+1] + pq[tid*4+2] + pq[tid*4+3];
            float mean = s * (1.f/64.f);
            float var  = q * (1.f/64.f) - mean*mean;
            means[tid] = mean;
            invs[tid]  = rsqrtf(var + 1e-5f);
        }
        __syncthreads();

        // apply LN1 -> H cols 64..127 (bf16 hi/lo)
        #pragma unroll
        for (int mt = 0; mt < 2; mt++)
            #pragma unroll
            for (int nt = 0; nt < 2; nt++) {
                int rr = wM*32 + mt*16 + r;
                int cc = wN*16 + nt*8 + c2;
                float m0 = means[rr], i0 = invs[rr];
                float y0 = (accA[mt][nt][0] - m0)*i0*gbuf[cc]   + gbuf[64+cc];
                float y1 = (accA[mt][nt][1] - m0)*i0*gbuf[cc+1] + gbuf[64+cc+1];
                uint32_t hi, lo;
                split2(y0, y1, hi, lo);
                *(uint32_t*)(Hh + rr*136 + 64 + cc) = hi;
                *(uint32_t*)(Hl + rr*136 + 64 + cc) = lo;
                float m1 = means[rr+8], i1 = invs[rr+8];
                float y2 = (accA[mt][nt][2] - m1)*i1*gbuf[cc]   + gbuf[64+cc];
                float y3 = (accA[mt][nt][3] - m1)*i1*gbuf[cc+1] + gbuf[64+cc+1];
                split2(y2, y3, hi, lo);
                *(uint32_t*)(Hh + (rr+8)*136 + 64 + cc) = hi;
                *(uint32_t*)(Hl + (rr+8)*136 + 64 + cc) = lo;
            }
        __syncthreads();

        // ---- Stage B: [x;m] @ w1^T  (M64,N128,K128) ----
        float accB[2][4][4];
        #pragma unroll
        for (int i = 0; i < 2; i++)
            #pragma unroll
            for (int j = 0; j < 4; j++)
                #pragma unroll
                for (int q = 0; q < 4; q++) accB[i][j][q] = 0.f;
        warp_gemm<4,8>(accB, Hh, Hl, 136, wM*32, W1H, W1L, 136, wN*32, lane);

        // relu -> H1 (bf16 hi/lo)
        #pragma unroll
        for (int mt = 0; mt < 2; mt++)
            #pragma unroll
            for (int nt = 0; nt < 4; nt++) {
                int rr = wM*32 + mt*16 + r;
                int cc = wN*32 + nt*8 + c2;
                uint32_t hi, lo;
                split2(fmaxf(accB[mt][nt][0], 0.f), fmaxf(accB[mt][nt][1], 0.f), hi, lo);
                *(uint32_t*)(H1h + rr*136 + cc) = hi;
                *(uint32_t*)(H1l + rr*136 + cc) = lo;
                split2(fmaxf(accB[mt][nt][2], 0.f), fmaxf(accB[mt][nt][3], 0.f), hi, lo);
                *(uint32_t*)(H1h + (rr+8)*136 + cc) = hi;
                *(uint32_t*)(H1l + (rr+8)*136 + cc) = lo;
            }
        __syncthreads();

        // ---- Stage C: h1 @ w2^T  (M64,N64,K128) ----
        float accC[2][2][4];
        #pragma unroll
        for (int i = 0; i < 2; i++)
            #pragma unroll
            for (int j = 0; j < 2; j++)
                #pragma unroll
                for (int q = 0; q < 4; q++) accC[i][j][q] = 0.f;
        warp_gemm<2,8>(accC, H1h, H1l, 136, wM*32, W2H, W2L, 136, wN*16, lane);

        // LN2 stats
        #pragma unroll
        for (int mt = 0; mt < 2; mt++) {
            float s0 = 0.f, q0 = 0.f, s1 = 0.f, q1 = 0.f;
            #pragma unroll
            for (int nt = 0; nt < 2; nt++) {
                float a0 = accC[mt][nt][0], a1 = accC[mt][nt][1];
                float a2 = accC[mt][nt][2], a3 = accC[mt][nt][3];
                s0 += a0 + a1; q0 += a0*a0 + a1*a1;
                s1 += a2 + a3; q1 += a2*a2 + a3*a3;
            }
            quad_reduce2(s0, q0);
            quad_reduce2(s1, q1);
            if ((lane & 3) == 0) {
                int rr = wM*32 + mt*16 + r;
                ps[rr*4 + wN] = s0;      pq[rr*4 + wN] = q0;
                ps[(rr+8)*4 + wN] = s1;  pq[(rr+8)*4 + wN] = q1;
            }
        }
        __syncthreads();
        if (tid < 64) {
            float s = ps[tid*4] + ps[tid*4+1] + ps[tid*4+2] + ps[tid*4+3];
            float q = pq[tid*4] + pq[tid*4+1] + pq[tid*4+2] + pq[tid*4+3];
            float mean = s * (1.f/64.f);
            float var  = q * (1.f/64.f) - mean*mean;
            means[tid] = mean;
            invs[tid]  = rsqrtf(var + 1e-5f);
        }
        __syncthreads();

        // LN2 + residual -> gmem (sector-aligned 8B stores)
        #pragma unroll
        for (int mt = 0; mt < 2; mt++)
            #pragma unroll
            for (int nt = 0; nt < 2; nt++) {
                int rr = wM*32 + mt*16 + r;
                int cc = wN*16 + nt*8 + c2;
                float m0 = means[rr], i0 = invs[rr];
                float2 xv = *(const float2*)(xb + rr*66 + cc);
                float2 o0;
                o0.x = xv.x + (accC[mt][nt][0] - m0)*i0*gbuf[128+cc]   + gbuf[192+cc];
                o0.y = xv.y + (accC[mt][nt][1] - m0)*i0*gbuf[128+cc+1] + gbuf[192+cc+1];
                *(float2*)(out + (size_t)(tok0 + rr)*64 + cc) = o0;
                float m1 = means[rr+8], i1 = invs[rr+8];
                float2 xw = *(const float2*)(xb + (rr+8)*66 + cc);
                float2 o1;
                o1.x = xw.x + (accC[mt][nt][2] - m1)*i1*gbuf[128+cc]   + gbuf[192+cc];
                o1.y = xw.y + (accC[mt][nt][3] - m1)*i1*gbuf[128+cc+1] + gbuf[192+cc+1];
                *(float2*)(out + (size_t)(tok0 + rr + 8)*64 + cc) = o1;
            }
        __syncthreads();   // protect act buffers/xbuf before next tile
    }
}

// ---------------- launch ----------------
extern "C" void kernel_launch(void* const* d_in, const int* in_sizes, int n_in,
                              void* d_out, int out_size) {
    const float* x   = (const float*)d_in[0];
    const float* src = (const float*)d_in[1];
    const float* wq  = (const float*)d_in[2];
    const float* wk  = (const float*)d_in[3];
    const float* wv  = (const float*)d_in[4];
    const float* wm  = (const float*)d_in[5];
    const float* w1  = (const float*)d_in[6];
    const float* w2  = (const float*)d_in[7];
    const float* g1  = (const float*)d_in[8];
    const float* b1  = (const float*)d_in[9];
    const float* g2  = (const float*)d_in[10];
    const float* b2  = (const float*)d_in[11];
    float* out = (float*)d_out;

    cudaFuncSetAttribute(k1_kv,   cudaFuncAttributeMaxDynamicSharedMemorySize, SMEM1_B);
    cudaFuncSetAttribute(k2_attn, cudaFuncAttributeMaxDynamicSharedMemorySize, SMEM2_B);
    cudaFuncSetAttribute(k3_mma,  cudaFuncAttributeMaxDynamicSharedMemorySize, SMEM3M);

    k0_zero<<<512, 256>>>();
    k1_kv<<<dim3(SS/256, NHD), 256, SMEM1_B>>>(src, wk, wv);
    k2_attn<<<dim3(LL/64, NHD), 256, SMEM2_B>>>(x, wq);
    k3_mma<<<148, 256, SMEM3M>>>(x, wm, w1, w2, g1, b1, g2, b2, out);
}